// round 8
// baseline (speedup 1.0000x reference)
#include <cuda_runtime.h>
#include <cstdint>

#define BATCH   8192
#define LMAX    100
#define DIM     128
#define DIM2    256

// Scratch (device globals: no allocation allowed)
__device__ float g_H [BATCH * DIM2];
__device__ float g_T1[BATCH * DIM2];
__device__ float g_T2[BATCH * DIM2];

#define FMA2(acc, a, b) \
    asm("fma.rn.f32x2 %0, %1, %2, %0;" : "+l"(acc) : "l"(a), "l"(b))
#define PACKDUP(out, f) \
    asm("mov.b64 %0, {%1, %1};" : "=l"(out) : "r"(__float_as_uint(f)))

// ---- dynamic smem layout for attn_kernel (bytes) ----
#define OFF_BUF   0                       // row buffer: LMAX*DIM floats = 51200
#define OFF_IT    (LMAX * DIM * 4)        // 51200: items, LMAX ints (400 -> pad 416)
#define OFF_HU    (OFF_IT + 416)          // 51616: h_u, DIM floats (512)
#define OFF_SC    (OFF_HU + DIM * 4)      // 52128: scores/weights, LMAX floats (400->416)
#define OFF_RED   (OFF_SC + 416)          // 52544: reductions, 8 floats (32)
#define OFF_MBAR  (OFF_RED + 32)          // 52576: mbarrier (8, 8-aligned)
#define ATTN_SMEM (OFF_MBAR + 16)         // 52592 total -> 4 CTAs/SM (228KB carveout)

__device__ __forceinline__ uint32_t s2u(const void* p) {
    uint32_t a;
    asm("{ .reg .u64 t; cvta.to.shared.u64 t, %1; cvt.u32.u64 %0, t; }"
        : "=r"(a) : "l"(p));
    return a;
}

__device__ __forceinline__ void bulk_g2s(uint32_t dst_smem, const void* src,
                                         uint32_t bytes, uint32_t mbar) {
    asm volatile(
        "cp.async.bulk.shared::cta.global.mbarrier::complete_tx::bytes "
        "[%0], [%1], %2, [%3];"
        :: "r"(dst_smem), "l"(src), "r"(bytes), "r"(mbar) : "memory");
}

__device__ __forceinline__ void mbar_expect_tx(uint32_t mbar, uint32_t bytes) {
    asm volatile("mbarrier.arrive.expect_tx.shared.b64 _, [%0], %1;"
                 :: "r"(mbar), "r"(bytes) : "memory");
}

__device__ __forceinline__ void mbar_wait(uint32_t mbar, uint32_t parity) {
    asm volatile(
        "{\n\t"
        ".reg .pred P;\n\t"
        "W_%=:\n\t"
        "mbarrier.try_wait.parity.acquire.cta.shared::cta.b64 P, [%0], %1, 0x989680;\n\t"
        "@P bra D_%=;\n\t"
        "bra W_%=;\n\t"
        "D_%=:\n\t"
        "}"
        :: "r"(mbar), "r"(parity) : "memory");
}

// ---------------------------------------------------------------------------
// Kernel 1: attention via hardware bulk-copy gathers.  One CTA (128 thr) per
// bundle, 4 CTAs/SM.  Phase A: async-copy the n A-rows (512 B each) into the
// smem row buffer via cp.async.bulk + one mbarrier expect_tx; compute scores
// + softmax (no max-subtraction: scores are O(1), ratio identical).  Phase B:
// reuse the buffer for the n emb_i rows; weighted sum.  Warps HW-sleep on the
// mbarrier while ~100 copies/CTA stream at the L2 cap.
// ---------------------------------------------------------------------------
__global__ __launch_bounds__(128) void attn_kernel(
    const int*  __restrict__ x_u,
    const int*  __restrict__ x_b,
    const int*  __restrict__ items,
    const int*  __restrict__ mask,     // int32 prefix flags
    const float* __restrict__ emb_u,
    const float* __restrict__ emb_i,
    const float* __restrict__ emb_b,
    const float* __restrict__ A)
{
    extern __shared__ __align__(16) char smem[];
    float* buf   = (float*)(smem + OFF_BUF);
    int*   s_it  = (int*)  (smem + OFF_IT);
    float* s_hu  = (float*)(smem + OFF_HU);
    float* s_sc  = (float*)(smem + OFF_SC);
    float* s_red = (float*)(smem + OFF_RED);
    const uint32_t mbar  = s2u(smem + OFF_MBAR);
    const uint32_t buf_s = s2u(smem + OFF_BUF);

    const int b    = blockIdx.x;
    const int tid  = threadIdx.x;
    const int warp = tid >> 5;
    const int lane = tid & 31;

    if (tid == 0)
        asm volatile("mbarrier.init.shared.b64 [%0], 1;" :: "r"(mbar) : "memory");

    const int xu = x_u[b];
    const int xb = x_b[b];
    s_hu[tid] = emb_u[(size_t)xu * DIM + tid];
    const float hbv = emb_b[(size_t)xb * DIM + tid];

    int v = 0;
    if (tid < LMAX) {
        v = (mask[(size_t)b * LMAX + tid] != 0) ? 1 : 0;
        s_it[tid] = items[(size_t)b * LMAX + tid];
    }
    #pragma unroll
    for (int o = 16; o > 0; o >>= 1)
        v += __shfl_xor_sync(0xffffffffu, v, o);
    if (lane == 0) s_red[warp] = (float)v;
    __syncthreads();                      // mbar init + s_it + counts visible
    const int n = (int)(s_red[0] + s_red[1] + s_red[2] + s_red[3]);  // >= 10

    // ---- phase A: bulk-copy the n A-rows into buf ----
    if (tid == 0) mbar_expect_tx(mbar, (uint32_t)n * 512u);
    __syncthreads();
    if (lane == 0)
        for (int r = warp; r < n; r += 4)
            bulk_g2s(buf_s + (uint32_t)r * 512u, A + (size_t)s_it[r] * DIM, 512u, mbar);
    mbar_wait(mbar, 0);

    // ---- scores from smem: warp per item, 5-shfl reduce ----
    const float4 hu4 = *(const float4*)(s_hu + lane * 4);
    for (int l = warp; l < n; l += 4) {
        const float4 r4 = *(const float4*)(buf + l * DIM + lane * 4);
        float p = hu4.x * r4.x + hu4.y * r4.y + hu4.z * r4.z + hu4.w * r4.w;
        #pragma unroll
        for (int o = 16; o > 0; o >>= 1)
            p += __shfl_xor_sync(0xffffffffu, p, o);
        if (lane == 0) s_sc[l] = p;
    }
    __syncthreads();

    // ---- softmax (no max shift; scores O(1)) ----
    float e = (tid < n) ? __expf(s_sc[tid]) : 0.f;
    float se = e;
    #pragma unroll
    for (int o = 16; o > 0; o >>= 1)
        se += __shfl_xor_sync(0xffffffffu, se, o);
    if (lane == 0) s_red[4 + warp] = se;
    __syncthreads();
    const float tot = s_red[4] + s_red[5] + s_red[6] + s_red[7];
    if (tid < n) s_sc[tid] = e / tot;
    __syncthreads();                      // all buf reads done -> safe to reuse

    // ---- phase B: bulk-copy the n emb_i rows into buf ----
    if (tid == 0) mbar_expect_tx(mbar, (uint32_t)n * 512u);
    __syncthreads();
    if (lane == 0)
        for (int r = warp; r < n; r += 4)
            bulk_g2s(buf_s + (uint32_t)r * 512u, emb_i + (size_t)s_it[r] * DIM, 512u, mbar);
    mbar_wait(mbar, 1);

    // ---- weighted sum: thread tid owns feature dim tid ----
    float acc = 0.f;
    #pragma unroll 4
    for (int l = 0; l < n; l++)
        acc += s_sc[l] * buf[l * DIM + tid];

    float* Hrow = g_H + (size_t)b * DIM2;
    Hrow[tid]       = s_hu[tid];
    Hrow[DIM + tid] = hbv + acc;
}

// ---------------------------------------------------------------------------
// Kernel 2: Y = leaky_relu(X[M,256] @ W[256,256]^T + b).  f32x2 packed GEMM.
// BM=64, BN=128, BK=32, 256 threads, microtile 4(M) x 8(N) as 4x4 f32x2 pairs.
// ---------------------------------------------------------------------------
__global__ __launch_bounds__(256, 2) void mlp_gemm(
    const float* __restrict__ X,
    const float* __restrict__ W,
    const float* __restrict__ bias,
    float*       __restrict__ Y)
{
    constexpr int BM = 64, BN = 128, BK = 32;
    constexpr int XP = 33;               // Xs pitch
    constexpr int WP = 132;              // Ws_t pitch (mult of 4 for LDS.128)
    __shared__ float Xs  [BM * XP];
    __shared__ __align__(16) float Ws_t[BK * WP];

    const int bn0 = blockIdx.x * BN;
    const int bm0 = blockIdx.y * BM;
    const int tid = threadIdx.x;
    const int tx  = tid & 15;
    const int ty  = tid >> 4;
    const int lr  = tid >> 3;            // 0..31
    const int lc  = (tid & 7) * 4;       // 0,4,...,28

    unsigned long long acc[4][4];
    #pragma unroll
    for (int m = 0; m < 4; m++)
        #pragma unroll
        for (int np = 0; np < 4; np++) acc[m][np] = 0ull;

    for (int k0 = 0; k0 < DIM2; k0 += BK) {
        #pragma unroll
        for (int r = 0; r < BM; r += 32) {
            const float4 x4 = *(const float4*)(X + (size_t)(bm0 + lr + r) * DIM2 + k0 + lc);
            float* d = Xs + (lr + r) * XP + lc;
            d[0] = x4.x; d[1] = x4.y; d[2] = x4.z; d[3] = x4.w;
        }
        #pragma unroll
        for (int r = 0; r < BN; r += 32) {
            const float4 w4 = *(const float4*)(W + (size_t)(bn0 + lr + r) * DIM2 + k0 + lc);
            Ws_t[(lc + 0) * WP + lr + r] = w4.x;
            Ws_t[(lc + 1) * WP + lr + r] = w4.y;
            Ws_t[(lc + 2) * WP + lr + r] = w4.z;
            Ws_t[(lc + 3) * WP + lr + r] = w4.w;
        }
        __syncthreads();

        #pragma unroll 8
        for (int k = 0; k < BK; k++) {
            unsigned long long a2[4];
            #pragma unroll
            for (int m = 0; m < 4; m++) {
                const float a = Xs[(ty * 4 + m) * XP + k];
                PACKDUP(a2[m], a);
            }
            const ulonglong2 wlo = *(const ulonglong2*)(Ws_t + k * WP + tx * 8);
            const ulonglong2 whi = *(const ulonglong2*)(Ws_t + k * WP + tx * 8 + 4);
            #pragma unroll
            for (int m = 0; m < 4; m++) {
                FMA2(acc[m][0], a2[m], wlo.x);
                FMA2(acc[m][1], a2[m], wlo.y);
                FMA2(acc[m][2], a2[m], whi.x);
                FMA2(acc[m][3], a2[m], whi.y);
            }
        }
        __syncthreads();
    }

    float bv[8];
    #pragma unroll
    for (int j = 0; j < 8; j++) bv[j] = bias[bn0 + tx * 8 + j];

    #pragma unroll
    for (int m = 0; m < 4; m++) {
        float o[8];
        #pragma unroll
        for (int np = 0; np < 4; np++) {
            o[np * 2 + 0] = __uint_as_float((unsigned)(acc[m][np] & 0xffffffffull));
            o[np * 2 + 1] = __uint_as_float((unsigned)(acc[m][np] >> 32));
        }
        float* yrow = Y + (size_t)(bm0 + ty * 4 + m) * DIM2 + bn0 + tx * 8;
        #pragma unroll
        for (int j4 = 0; j4 < 8; j4 += 4) {
            float4 vv;
            float t0 = o[j4 + 0] + bv[j4 + 0];
            float t1 = o[j4 + 1] + bv[j4 + 1];
            float t2 = o[j4 + 2] + bv[j4 + 2];
            float t3 = o[j4 + 3] + bv[j4 + 3];
            vv.x = t0 >= 0.f ? t0 : 0.01f * t0;
            vv.y = t1 >= 0.f ? t1 : 0.01f * t1;
            vv.z = t2 >= 0.f ? t2 : 0.01f * t2;
            vv.w = t3 >= 0.f ? t3 : 0.01f * t3;
            *(float4*)(yrow + j4) = vv;
        }
    }
}

// ---------------------------------------------------------------------------
// Kernel 3: out[m] = dot(X[m,:], out_w) + out_b.  One warp per row.
// ---------------------------------------------------------------------------
__global__ __launch_bounds__(256) void head_kernel(
    const float* __restrict__ X,
    const float* __restrict__ w3,
    const float* __restrict__ b3,
    float*       __restrict__ out)
{
    const int row  = blockIdx.x * 8 + (threadIdx.x >> 5);
    const int lane = threadIdx.x & 31;
    const float* xr = X + (size_t)row * DIM2;

    const float4 x1 = *(const float4*)(xr + lane * 4);
    const float4 x2 = *(const float4*)(xr + DIM + lane * 4);
    const float4 w1 = *(const float4*)(w3 + lane * 4);
    const float4 w2 = *(const float4*)(w3 + DIM + lane * 4);

    float s = x1.x * w1.x + x1.y * w1.y + x1.z * w1.z + x1.w * w1.w
            + x2.x * w2.x + x2.y * w2.y + x2.z * w2.z + x2.w * w2.w;
    #pragma unroll
    for (int o = 16; o > 0; o >>= 1)
        s += __shfl_xor_sync(0xffffffffu, s, o);
    if (lane == 0) out[row] = s + b3[0];
}

// ---------------------------------------------------------------------------
extern "C" void kernel_launch(void* const* d_in, const int* in_sizes, int n_in,
                              void* d_out, int out_size)
{
    const int*  x_u    = (const int*)   d_in[0];
    const int*  x_b    = (const int*)   d_in[1];
    const int*  items  = (const int*)   d_in[2];
    const int*  mask   = (const int*)   d_in[3];
    const float* emb_u = (const float*) d_in[4];
    const float* emb_i = (const float*) d_in[5];
    const float* emb_b = (const float*) d_in[6];
    const float* A     = (const float*) d_in[7];
    const float* fc1_w = (const float*) d_in[8];
    const float* fc1_b = (const float*) d_in[9];
    const float* fc2_w = (const float*) d_in[10];
    const float* fc2_b = (const float*) d_in[11];
    const float* out_w = (const float*) d_in[12];
    const float* out_b = (const float*) d_in[13];
    float* out = (float*)d_out;

    float *H, *T1, *T2;
    cudaGetSymbolAddress((void**)&H,  g_H);
    cudaGetSymbolAddress((void**)&T1, g_T1);
    cudaGetSymbolAddress((void**)&T2, g_T2);

    cudaFuncSetAttribute(attn_kernel,
                         cudaFuncAttributeMaxDynamicSharedMemorySize, ATTN_SMEM);
    attn_kernel<<<BATCH, 128, ATTN_SMEM>>>(x_u, x_b, items, mask,
                                           emb_u, emb_i, emb_b, A);

    dim3 ggrid(DIM2 / 128, BATCH / 64);   // (2, 128)
    mlp_gemm<<<ggrid, 256>>>(H,  fc1_w, fc1_b, T1);
    mlp_gemm<<<ggrid, 256>>>(T1, fc2_w, fc2_b, T2);

    head_kernel<<<BATCH / 8, 256>>>(T2, out_w, out_b, out);
}